// round 5
// baseline (speedup 1.0000x reference)
#include <cuda_runtime.h>

// ---------------------------------------------------------------------------
// Fully fused MLP-Mixer, round 4: E=2 (256 thr, 8 warps, 16 elems/CTA) with
// EXPLICIT cross-iteration software pipelining: gemm2 is skewed by one d-pair,
// so gemm2(i-1) FFMA2s (ready at body entry) interleave with gemm1(i) loads
// and the horizontal/hswish chain. Bias folded into gemm1 acc init, 1/6 folded
// into staged w2T. All inner products are packed fma.rn.f32x2.
// ---------------------------------------------------------------------------

#define MIX_EPS 1e-5f

// ---- SMEM layout (in floats) ----
#define OFF_W11   0        // 8192  (also fc0_w / fc1_w)
#define OFF_W12T  8192     // 256*36 = 9216
#define OFF_W21   17408    // 8192  (also fcout_w)
#define OFF_W22T  25600    // 9216
#define OFF_B11   34816    // 256   (also fc0_b / fc1_b)
#define OFF_B12   35072    // 32    (also fcout_b)
#define OFF_B21   35104    // 256
#define OFF_B22   35360    // 32
#define OFF_LN1G  35392
#define OFF_LN1B  35424
#define OFF_LN2G  35456
#define OFF_LN2B  35488
#define OFF_H     35520    // 16 elems * 1056
#define OFF_STATS 52416    // 8 warps * 2 elems * 64
#define SMEM_FLOATS 53440  // 213760 bytes

__device__ __forceinline__ float2 ffma2(float2 a, float2 b, float2 c) {
    unsigned long long au = *reinterpret_cast<unsigned long long*>(&a);
    unsigned long long bu = *reinterpret_cast<unsigned long long*>(&b);
    unsigned long long cu = *reinterpret_cast<unsigned long long*>(&c);
    unsigned long long du;
    asm("fma.rn.f32x2 %0, %1, %2, %3;" : "=l"(du) : "l"(au), "l"(bu), "l"(cu));
    return *reinterpret_cast<float2*>(&du);
}

__device__ __forceinline__ float2 fadd2(float2 a, float2 b) {
    unsigned long long au = *reinterpret_cast<unsigned long long*>(&a);
    unsigned long long bu = *reinterpret_cast<unsigned long long*>(&b);
    unsigned long long du;
    asm("add.rn.f32x2 %0, %1, %2;" : "=l"(du) : "l"(au), "l"(bu));
    return *reinterpret_cast<float2*>(&du);
}

// gemm1 + hswish for d-pair (d, d+1) on both elements. hp outputs are the
// hardswish values WITHOUT the 1/6 (folded into w2T), broadcast into float2.
__device__ __forceinline__ void g1pair(
    const float* sW1, const float* sB1, int d,
    const float2* l0, const float2* l1,
    float2& hpA0, float2& hpA1, float2& hpB0, float2& hpB1)
{
    float2 bias2 = *reinterpret_cast<const float2*>(sB1 + d);
    const float4* wA = reinterpret_cast<const float4*>(sW1 + d * 32);
    const float4* wB = wA + 8;

    float2 pA0 = make_float2(bias2.x, 0.f), pA0b = make_float2(0.f, 0.f);
    float2 pA1 = make_float2(bias2.x, 0.f), pA1b = make_float2(0.f, 0.f);
    float2 pB0 = make_float2(bias2.y, 0.f), pB0b = make_float2(0.f, 0.f);
    float2 pB1 = make_float2(bias2.y, 0.f), pB1b = make_float2(0.f, 0.f);
    #pragma unroll
    for (int qq = 0; qq < 8; qq++) {
        float4 wa = wA[qq];
        float4 wb = wB[qq];
        float2 waxy = make_float2(wa.x, wa.y), wazw = make_float2(wa.z, wa.w);
        float2 wbxy = make_float2(wb.x, wb.y), wbzw = make_float2(wb.z, wb.w);
        pA0  = ffma2(l0[2 * qq],     waxy, pA0);
        pA0b = ffma2(l0[2 * qq + 1], wazw, pA0b);
        pA1  = ffma2(l1[2 * qq],     waxy, pA1);
        pA1b = ffma2(l1[2 * qq + 1], wazw, pA1b);
        pB0  = ffma2(l0[2 * qq],     wbxy, pB0);
        pB0b = ffma2(l0[2 * qq + 1], wbzw, pB0b);
        pB1  = ffma2(l1[2 * qq],     wbxy, pB1);
        pB1b = ffma2(l1[2 * qq + 1], wbzw, pB1b);
    }
    float2 sA0 = fadd2(pA0, pA0b);
    float2 sA1 = fadd2(pA1, pA1b);
    float2 sB0 = fadd2(pB0, pB0b);
    float2 sB1v = fadd2(pB1, pB1b);
    float vA0 = sA0.x + sA0.y;
    float vA1 = sA1.x + sA1.y;
    float vB0 = sB0.x + sB0.y;
    float vB1 = sB1v.x + sB1v.y;
    float hA0 = vA0 * fminf(fmaxf(vA0 + 3.0f, 0.0f), 6.0f);
    float hA1 = vA1 * fminf(fmaxf(vA1 + 3.0f, 0.0f), 6.0f);
    float hB0 = vB0 * fminf(fmaxf(vB0 + 3.0f, 0.0f), 6.0f);
    float hB1 = vB1 * fminf(fmaxf(vB1 + 3.0f, 0.0f), 6.0f);
    hpA0 = make_float2(hA0, hA0);
    hpA1 = make_float2(hA1, hA1);
    hpB0 = make_float2(hB0, hB0);
    hpB1 = make_float2(hB1, hB1);
}

// gemm2 accumulate for d-pair (d, d+1) using precomputed hp values.
__device__ __forceinline__ void g2pair(
    const float* sW2T, int d,
    float2 hpA0, float2 hpA1, float2 hpB0, float2 hpB1,
    float2* out0, float2* out1)
{
    const float4* w2A = reinterpret_cast<const float4*>(sW2T + d * 36);
    const float4* w2B = reinterpret_cast<const float4*>(sW2T + d * 36 + 36);
    #pragma unroll
    for (int qq = 0; qq < 8; qq++) {
        float4 wa = w2A[qq];
        float4 wb = w2B[qq];
        float2 waxy = make_float2(wa.x, wa.y), wazw = make_float2(wa.z, wa.w);
        float2 wbxy = make_float2(wb.x, wb.y), wbzw = make_float2(wb.z, wb.w);
        out0[2 * qq]     = ffma2(hpA0, waxy, out0[2 * qq]);
        out0[2 * qq + 1] = ffma2(hpA0, wazw, out0[2 * qq + 1]);
        out1[2 * qq]     = ffma2(hpA1, waxy, out1[2 * qq]);
        out1[2 * qq + 1] = ffma2(hpA1, wazw, out1[2 * qq + 1]);
        out0[2 * qq]     = ffma2(hpB0, wbxy, out0[2 * qq]);
        out0[2 * qq + 1] = ffma2(hpB0, wbzw, out0[2 * qq + 1]);
        out1[2 * qq]     = ffma2(hpB1, wbxy, out1[2 * qq]);
        out1[2 * qq + 1] = ffma2(hpB1, wbzw, out1[2 * qq + 1]);
    }
}

// One mixing branch on two elements owned by this warp (E=2), pipelined.
template <bool TOKEN>
__device__ __forceinline__ void mix_branch(
    float* h0, float* h1,
    const float* sW1, const float* sW2T,
    const float* sB1, const float* sB2,
    const float* sG, const float* sBb,
    float* st0, float* st1, int lane)
{
    float2 l0[16], l1[16];

    if (TOKEN) {
        float s0 = 0.f, q0 = 0.f, s1 = 0.f, q1 = 0.f;
        #pragma unroll
        for (int j = 0; j < 32; j++) {
            float v = h0[lane * 33 + j]; s0 += v; q0 += v * v;
            float w = h1[lane * 33 + j]; s1 += w; q1 += w * w;
        }
        float m0 = s0 * 0.03125f, m1 = s1 * 0.03125f;
        float r0 = rsqrtf(fmaxf(q0 * 0.03125f - m0 * m0, 0.f) + MIX_EPS);
        float r1 = rsqrtf(fmaxf(q1 * 0.03125f - m1 * m1, 0.f) + MIX_EPS);
        st0[lane] = m0; st0[32 + lane] = r0;
        st1[lane] = m1; st1[32 + lane] = r1;
        __syncwarp();
        float gj = sG[lane], bj = sBb[lane];
        #pragma unroll
        for (int t = 0; t < 16; t++) {
            int k0 = 2 * t, k1 = 2 * t + 1;
            float mA = st0[k0], rA = st0[32 + k0];
            float mB = st0[k1], rB = st0[32 + k1];
            l0[t] = make_float2((h0[k0 * 33 + lane] - mA) * rA * gj + bj,
                                (h0[k1 * 33 + lane] - mB) * rB * gj + bj);
            float mC = st1[k0], rC = st1[32 + k0];
            float mD = st1[k1], rD = st1[32 + k1];
            l1[t] = make_float2((h1[k0 * 33 + lane] - mC) * rC * gj + bj,
                                (h1[k1 * 33 + lane] - mD) * rD * gj + bj);
        }
    } else {
        float s0 = 0.f, q0 = 0.f, s1 = 0.f, q1 = 0.f;
        #pragma unroll
        for (int j = 0; j < 32; j++) {
            float v = h0[lane * 33 + j]; s0 += v; q0 += v * v;
            float w = h1[lane * 33 + j]; s1 += w; q1 += w * w;
        }
        float m0 = s0 * 0.03125f, m1 = s1 * 0.03125f;
        float r0 = rsqrtf(fmaxf(q0 * 0.03125f - m0 * m0, 0.f) + MIX_EPS);
        float r1 = rsqrtf(fmaxf(q1 * 0.03125f - m1 * m1, 0.f) + MIX_EPS);
        #pragma unroll
        for (int t = 0; t < 16; t++) {
            int j0 = 2 * t, j1 = 2 * t + 1;
            float g0 = sG[j0], g1 = sG[j1], bb0 = sBb[j0], bb1 = sBb[j1];
            l0[t] = make_float2((h0[lane * 33 + j0] - m0) * r0 * g0 + bb0,
                                (h0[lane * 33 + j1] - m0) * r0 * g1 + bb1);
            l1[t] = make_float2((h1[lane * 33 + j0] - m1) * r1 * g0 + bb0,
                                (h1[lane * 33 + j1] - m1) * r1 * g1 + bb1);
        }
    }

    float2 out0[16], out1[16];
    #pragma unroll
    for (int t = 0; t < 16; t++) {
        float2 bv = *reinterpret_cast<const float2*>(sB2 + 2 * t);
        out0[t] = bv; out1[t] = bv;
    }

    // ---- software-pipelined hidden loop: gemm2 skewed by one d-pair ----
    float2 hpA0, hpA1, hpB0, hpB1;
    g1pair(sW1, sB1, 0, l0, l1, hpA0, hpA1, hpB0, hpB1);
    for (int d = 2; d < 256; d += 2) {
        float2 nA0, nA1, nB0, nB1;
        g1pair(sW1, sB1, d, l0, l1, nA0, nA1, nB0, nB1);
        g2pair(sW2T, d - 2, hpA0, hpA1, hpB0, hpB1, out0, out1);
        hpA0 = nA0; hpA1 = nA1; hpB0 = nB0; hpB1 = nB1;
    }
    g2pair(sW2T, 254, hpA0, hpA1, hpB0, hpB1, out0, out1);

    if (TOKEN) {
        #pragma unroll
        for (int t = 0; t < 16; t++) {
            h0[(2 * t) * 33 + lane]     += out0[t].x;
            h0[(2 * t + 1) * 33 + lane] += out0[t].y;
            h1[(2 * t) * 33 + lane]     += out1[t].x;
            h1[(2 * t + 1) * 33 + lane] += out1[t].y;
        }
    } else {
        #pragma unroll
        for (int t = 0; t < 16; t++) {
            h0[lane * 33 + 2 * t]     += out0[t].x;
            h0[lane * 33 + 2 * t + 1] += out0[t].y;
            h1[lane * 33 + 2 * t]     += out1[t].x;
            h1[lane * 33 + 2 * t + 1] += out1[t].y;
        }
    }
    __syncwarp();
}

extern __shared__ float smem[];

__global__ __launch_bounds__(256, 1)
void mixer_kernel(
    const float* __restrict__ x,
    const float* __restrict__ conv_w, const float* __restrict__ conv_b,
    const float* __restrict__ fc0_w,  const float* __restrict__ fc0_b,
    const float* __restrict__ ln1_g,  const float* __restrict__ ln1_b,
    const float* __restrict__ w11,    const float* __restrict__ b11,
    const float* __restrict__ w12,    const float* __restrict__ b12,
    const float* __restrict__ ln2_g,  const float* __restrict__ ln2_b,
    const float* __restrict__ w21,    const float* __restrict__ b21,
    const float* __restrict__ w22,    const float* __restrict__ b22,
    const float* __restrict__ fc1_w,  const float* __restrict__ fc1_b,
    const float* __restrict__ fcout_w,const float* __restrict__ fcout_b,
    float* __restrict__ out, int B)
{
    const int tid = threadIdx.x;
    const int lane = tid & 31;
    const int wid = tid >> 5;

    float* sW11  = smem + OFF_W11;
    float* sW12T = smem + OFF_W12T;
    float* sW21  = smem + OFF_W21;
    float* sW22T = smem + OFF_W22T;
    float* sB11  = smem + OFF_B11;
    float* sB12  = smem + OFF_B12;
    float* sB21  = smem + OFF_B21;
    float* sB22  = smem + OFF_B22;
    float* sLn1g = smem + OFF_LN1G;
    float* sLn1b = smem + OFF_LN1B;
    float* sLn2g = smem + OFF_LN2G;
    float* sLn2b = smem + OFF_LN2B;
    float* sH    = smem + OFF_H;
    float* sStats= smem + OFF_STATS;

    const int e0 = blockIdx.x * 16 + wid * 2;
    const int e1 = e0 + 1;
    const bool act0 = (e0 < B), act1 = (e1 < B);
    float* h0 = sH + (wid * 2) * 1056;
    float* h1 = h0 + 1056;
    float* st0 = sStats + wid * 128;
    float* st1 = st0 + 64;

    // ---- stage fc0 weights, then preprocess (conv1x1 + fc0) ----
    for (int i = tid; i < 1024; i += 256) sW11[i] = fc0_w[i];
    if (tid < 32) sB11[tid] = fc0_b[tid];
    __syncthreads();

    {
        const float cw0 = conv_w[0], cw1 = conv_w[1], cw2 = conv_w[2];
        const float cb  = conv_b[0];
        #pragma unroll
        for (int e = 0; e < 2; e++) {
            const int eb = e0 + e;
            if (eb >= B) break;
            float* hh = e ? h1 : h0;
            const float* xb = x + (size_t)eb * 3072 + lane * 32;
            float2 gp[16];
            #pragma unroll
            for (int q = 0; q < 8; q++) {
                float4 v0 = *reinterpret_cast<const float4*>(xb + q * 4);
                float4 v1 = *reinterpret_cast<const float4*>(xb + 1024 + q * 4);
                float4 v2 = *reinterpret_cast<const float4*>(xb + 2048 + q * 4);
                float g0 = cw0 * v0.x + cw1 * v1.x + cw2 * v2.x + cb;
                float g1 = cw0 * v0.y + cw1 * v1.y + cw2 * v2.y + cb;
                float g2 = cw0 * v0.z + cw1 * v1.z + cw2 * v2.z + cb;
                float g3 = cw0 * v0.w + cw1 * v1.w + cw2 * v2.w + cb;
                gp[2 * q]     = make_float2(g0, g1);
                gp[2 * q + 1] = make_float2(g2, g3);
            }
            for (int j = 0; j < 32; j++) {
                const float4* wq = reinterpret_cast<const float4*>(sW11 + j * 32);
                float2 acc = make_float2(0.f, 0.f), accb = make_float2(0.f, 0.f);
                #pragma unroll
                for (int q = 0; q < 8; q++) {
                    float4 w = wq[q];
                    acc  = ffma2(gp[2 * q],     make_float2(w.x, w.y), acc);
                    accb = ffma2(gp[2 * q + 1], make_float2(w.z, w.w), accb);
                }
                float2 sv = fadd2(acc, accb);
                hh[lane * 33 + j] = sv.x + sv.y + sB11[j];
            }
        }
    }
    __syncthreads();

    // ---- 8 layers x 2 repeats ----
    for (int l = 0; l < 8; l++) {
        // stage this layer's weights (w12/w22 transposed to [256][36], /6)
        {
            const float4* s1 = reinterpret_cast<const float4*>(w11 + l * 8192);
            float4* d1 = reinterpret_cast<float4*>(sW11);
            for (int i = tid; i < 2048; i += 256) d1[i] = s1[i];
            const float4* s2 = reinterpret_cast<const float4*>(w21 + l * 8192);
            float4* d2 = reinterpret_cast<float4*>(sW21);
            for (int i = tid; i < 2048; i += 256) d2[i] = s2[i];
            const float* g12 = w12 + l * 8192;
            for (int i = tid; i < 8192; i += 256) {
                int d = i & 255, k = i >> 8;
                sW12T[d * 36 + k] = g12[i] * (1.0f / 6.0f);
            }
            const float* g22 = w22 + l * 8192;
            for (int i = tid; i < 8192; i += 256) {
                int d = i & 255, k = i >> 8;
                sW22T[d * 36 + k] = g22[i] * (1.0f / 6.0f);
            }
            if (tid < 256) { sB11[tid] = b11[l * 256 + tid]; sB21[tid] = b21[l * 256 + tid]; }
            if (tid < 32) {
                sB12[tid]  = b12[l * 32 + tid];
                sB22[tid]  = b22[l * 32 + tid];
                sLn1g[tid] = ln1_g[l * 32 + tid];
                sLn1b[tid] = ln1_b[l * 32 + tid];
                sLn2g[tid] = ln2_g[l * 32 + tid];
                sLn2b[tid] = ln2_b[l * 32 + tid];
            }
        }
        __syncthreads();

        for (int rep = 0; rep < 2; rep++) {
            mix_branch<true >(h0, h1, sW11, sW12T, sB11, sB12, sLn1g, sLn1b, st0, st1, lane);
            mix_branch<false>(h0, h1, sW21, sW22T, sB21, sB22, sLn2g, sLn2b, st0, st1, lane);
        }
        __syncthreads();
    }

    // ---- head: fc1 + hardswish + avgpool(32) + fcout ----
    {
        const float4* s1 = reinterpret_cast<const float4*>(fc1_w);
        float4* d1 = reinterpret_cast<float4*>(sW11);
        for (int i = tid; i < 1024; i += 256) d1[i] = s1[i];
        for (int i = tid; i < 1280; i += 256) sW21[i] = fcout_w[i];
        if (tid < 128) sB11[tid] = fc1_b[tid];
        if (tid < 10)  sB12[tid] = fcout_b[tid];
    }
    __syncthreads();

    #pragma unroll
    for (int e = 0; e < 2; e++) {
        const bool act = e ? act1 : act0;
        if (!act) break;
        float* hh = e ? h1 : h0;
        float2 ap[16];
        #pragma unroll
        for (int t = 0; t < 16; t++)
            ap[t] = make_float2(hh[lane * 33 + 2 * t], hh[lane * 33 + 2 * t + 1]);
        float pool[4] = {0.f, 0.f, 0.f, 0.f};
        for (int d = 0; d < 128; d++) {
            const float4* wq = reinterpret_cast<const float4*>(sW11 + d * 32);
            float2 acc = make_float2(0.f, 0.f), accb = make_float2(0.f, 0.f);
            #pragma unroll
            for (int q = 0; q < 8; q++) {
                float4 w = wq[q];
                acc  = ffma2(ap[2 * q],     make_float2(w.x, w.y), acc);
                accb = ffma2(ap[2 * q + 1], make_float2(w.z, w.w), accb);
            }
            float2 sv = fadd2(acc, accb);
            float v = sv.x + sv.y + sB11[d];
            float y = v * fminf(fmaxf(v + 3.0f, 0.0f), 6.0f) * (1.0f / 6.0f);
            pool[d >> 5] += y;
        }
        #pragma unroll
        for (int p = 0; p < 4; p++) pool[p] *= (1.0f / 32.0f);
        const int eb = e ? e1 : e0;
        #pragma unroll
        for (int o = 0; o < 10; o++) {
            float4 wv = *reinterpret_cast<const float4*>(sW21 + o * 128 + lane * 4);
            float v = pool[0] * wv.x + pool[1] * wv.y + pool[2] * wv.z + pool[3] * wv.w;
            #pragma unroll
            for (int s = 16; s > 0; s >>= 1)
                v += __shfl_xor_sync(0xffffffffu, v, s);
            if (lane == 0) out[(size_t)eb * 10 + o] = v + sB12[o];
        }
    }
}

extern "C" void kernel_launch(void* const* d_in, const int* in_sizes, int n_in,
                              void* d_out, int out_size) {
    const float* x       = (const float*)d_in[0];
    const float* conv_w  = (const float*)d_in[1];
    const float* conv_b  = (const float*)d_in[2];
    const float* fc0_w   = (const float*)d_in[3];
    const float* fc0_b   = (const float*)d_in[4];
    const float* ln1_g   = (const float*)d_in[5];
    const float* ln1_b   = (const float*)d_in[6];
    const float* w11     = (const float*)d_in[7];
    const float* b11     = (const float*)d_in[8];
    const float* w12     = (const float*)d_in[9];
    const float* b12     = (const float*)d_in[10];
    const float* ln2_g   = (const float*)d_in[11];
    const float* ln2_b   = (const float*)d_in[12];
    const float* w21     = (const float*)d_in[13];
    const float* b21     = (const float*)d_in[14];
    const float* w22     = (const float*)d_in[15];
    const float* b22     = (const float*)d_in[16];
    const float* fc1_w   = (const float*)d_in[17];
    const float* fc1_b   = (const float*)d_in[18];
    const float* fcout_w = (const float*)d_in[19];
    const float* fcout_b = (const float*)d_in[20];
    float* out = (float*)d_out;

    const int B = in_sizes[0] / 3072;   // 3*32*32 floats per element
    const int blocks = (B + 15) / 16;
    const size_t smem_bytes = (size_t)SMEM_FLOATS * sizeof(float);

    cudaFuncSetAttribute(mixer_kernel,
                         cudaFuncAttributeMaxDynamicSharedMemorySize,
                         (int)smem_bytes);
    mixer_kernel<<<blocks, 256, smem_bytes>>>(
        x, conv_w, conv_b, fc0_w, fc0_b, ln1_g, ln1_b,
        w11, b11, w12, b12, ln2_g, ln2_b, w21, b21, w22, b22,
        fc1_w, fc1_b, fcout_w, fcout_b, out, B);
}

// round 6
// speedup vs baseline: 2.4740x; 2.4740x over previous
#include <cuda_runtime.h>
#include <cuda_bf16.h>

// ---------------------------------------------------------------------------
// MLP-Mixer on tensor cores (mma.sync m16n8k16 bf16, fp32 accum) with 3-pass
// bf16 hi/lo split for precision: C = Ah@Bh + Ah@Bl + Al@Bh.
// One warp owns one batch element (h [32][34] fp32 in SMEM). 8 warps/CTA.
// Per branch: gemm1 [32,32]@[32,256] -> hswish (in regs, D-frag == A-frag
// layout) -> gemm2 [32,256]@[256,32] -> residual. Weights staged per layer
// in SMEM as hi/lo bf16 planes with conflict-free strides (40 / 264 bf16).
// Pre (conv+fc0) and head (fc1+pool+fcout) stay on the fp32 FFMA2 path.
// ---------------------------------------------------------------------------

#define MIX_EPS 1e-5f

// ---- SMEM byte offsets ----
#define OFF_H     0         // 8 * 32*34 * 4 = 34816
#define OFF_ST    34816     // 8 * 64 * 4   = 2048
#define OFF_B1T   36864     // 256 f
#define OFF_B1C   37888     // 256 f
#define OFF_B2T   38912     // 32 f
#define OFF_B2C   39040     // 32 f
#define OFF_LN1G  39168
#define OFF_LN1B  39296
#define OFF_LN2G  39424
#define OFF_LN2B  39552
#define OFF_WT    39680     // weight region start
#define OFF_W1TH  39680     // 256*40*2 = 20480
#define OFF_W1TL  60160
#define OFF_W1CH  80640
#define OFF_W1CL  101120
#define OFF_W2TH  121600    // 32*264*2 = 16896
#define OFF_W2TL  138496
#define OFF_W2CH  155392
#define OFF_W2CL  172288
#define SMEM_BYTES 189184

__device__ __forceinline__ float2 ffma2(float2 a, float2 b, float2 c) {
    unsigned long long au = *reinterpret_cast<unsigned long long*>(&a);
    unsigned long long bu = *reinterpret_cast<unsigned long long*>(&b);
    unsigned long long cu = *reinterpret_cast<unsigned long long*>(&c);
    unsigned long long du;
    asm("fma.rn.f32x2 %0, %1, %2, %3;" : "=l"(du) : "l"(au), "l"(bu), "l"(cu));
    return *reinterpret_cast<float2*>(&du);
}
__device__ __forceinline__ float2 fadd2(float2 a, float2 b) {
    unsigned long long au = *reinterpret_cast<unsigned long long*>(&a);
    unsigned long long bu = *reinterpret_cast<unsigned long long*>(&b);
    unsigned long long du;
    asm("add.rn.f32x2 %0, %1, %2;" : "=l"(du) : "l"(au), "l"(bu));
    return *reinterpret_cast<float2*>(&du);
}

__device__ __forceinline__ void mma16816(float d[4], const unsigned a[4],
                                         unsigned b0, unsigned b1) {
    asm volatile(
        "mma.sync.aligned.m16n8k16.row.col.f32.bf16.bf16.f32 "
        "{%0,%1,%2,%3}, {%4,%5,%6,%7}, {%8,%9}, {%0,%1,%2,%3};\n"
        : "+f"(d[0]), "+f"(d[1]), "+f"(d[2]), "+f"(d[3])
        : "r"(a[0]), "r"(a[1]), "r"(a[2]), "r"(a[3]), "r"(b0), "r"(b1));
}

// One mixing branch for the warp's element using tensor cores.
// TOKEN: A = LN(h)^T (token mixing); else A = LN(h) (channel mixing).
// w2 planes are pre-scaled by 1/6 (hswish's 1/6 folded in).
template <bool TOKEN>
__device__ __forceinline__ void mix_branch_mma(
    float* h, float* st,
    const __nv_bfloat16* w1h, const __nv_bfloat16* w1l,
    const __nv_bfloat16* w2h, const __nv_bfloat16* w2l,
    const float* b1, const float* b2,
    const float* g, const float* bb, int lane)
{
    const int gid = lane >> 2;     // 0..7
    const int tg  = lane & 3;      // 0..3

    // ---- LN stats (lane = row) ----
    float s = 0.f, q = 0.f;
    #pragma unroll
    for (int j = 0; j < 32; j += 2) {
        float2 v = *reinterpret_cast<const float2*>(h + lane * 34 + j);
        s += v.x + v.y; q += v.x * v.x + v.y * v.y;
    }
    float m = s * 0.03125f;
    float r = rsqrtf(fmaxf(q * 0.03125f - m * m, 0.f) + MIX_EPS);
    st[lane] = m; st[32 + lane] = r;
    __syncwarp();

    // ---- A1 fragments (LN output, hi/lo bf16 split) ----
    unsigned a1h[2][2][4], a1l[2][2][4];
    #pragma unroll
    for (int mt = 0; mt < 2; mt++)
    #pragma unroll
    for (int kt = 0; kt < 2; kt++) {
        #pragma unroll
        for (int rr = 0; rr < 2; rr++) {
            int am = mt * 16 + gid + rr * 8;
            #pragma unroll
            for (int cc = 0; cc < 2; cc++) {
                int ak = kt * 16 + tg * 2 + cc * 8;
                float v0, v1;
                if (TOKEN) {
                    // A[am][ak] = LN(h)[ak][am]
                    float x0 = h[ak * 34 + am];
                    float x1 = h[(ak + 1) * 34 + am];
                    float gm = g[am], bm = bb[am];
                    v0 = (x0 - st[ak]) * st[32 + ak] * gm + bm;
                    v1 = (x1 - st[ak + 1]) * st[32 + ak + 1] * gm + bm;
                } else {
                    float2 x = *reinterpret_cast<const float2*>(h + am * 34 + ak);
                    float mm = st[am], ri = st[32 + am];
                    v0 = (x.x - mm) * ri * g[ak] + bb[ak];
                    v1 = (x.y - mm) * ri * g[ak + 1] + bb[ak + 1];
                }
                __nv_bfloat162 hi2 = __floats2bfloat162_rn(v0, v1);
                float l0 = v0 - __bfloat162float(hi2.x);
                float l1 = v1 - __bfloat162float(hi2.y);
                __nv_bfloat162 lo2 = __floats2bfloat162_rn(l0, l1);
                int ri2 = rr + cc * 2;
                a1h[mt][kt][ri2] = *reinterpret_cast<unsigned*>(&hi2);
                a1l[mt][kt][ri2] = *reinterpret_cast<unsigned*>(&lo2);
            }
        }
    }

    // ---- out accumulators [mt][ntO][4], init with bias b2 (per col) ----
    float outacc[2][4][4];
    #pragma unroll
    for (int ntO = 0; ntO < 4; ntO++) {
        int c = ntO * 8 + tg * 2;
        float bv0 = b2[c], bv1 = b2[c + 1];
        #pragma unroll
        for (int mt = 0; mt < 2; mt++) {
            outacc[mt][ntO][0] = bv0; outacc[mt][ntO][1] = bv1;
            outacc[mt][ntO][2] = bv0; outacc[mt][ntO][3] = bv1;
        }
    }

    // ---- hidden loop over DIM=256 in 4 chunks of 64 ----
    for (int nc = 0; nc < 4; nc++) {
        float dAcc[2][8][4];
        #pragma unroll
        for (int mt = 0; mt < 2; mt++)
        #pragma unroll
        for (int nt = 0; nt < 8; nt++)
        #pragma unroll
        for (int k = 0; k < 4; k++) dAcc[mt][nt][k] = 0.f;

        // gemm1: 3 split passes (Ah@Bh, Ah@Bl, Al@Bh)
        #pragma unroll
        for (int pass = 0; pass < 3; pass++) {
            const __nv_bfloat16* wp = (pass == 1) ? w1l : w1h;
            #pragma unroll
            for (int kt = 0; kt < 2; kt++) {
                #pragma unroll
                for (int nt = 0; nt < 8; nt++) {
                    int n = nc * 64 + nt * 8 + gid;
                    int k0 = kt * 16 + tg * 2;
                    unsigned b0  = *reinterpret_cast<const unsigned*>(wp + n * 40 + k0);
                    unsigned b1r = *reinterpret_cast<const unsigned*>(wp + n * 40 + k0 + 8);
                    const unsigned* af0 = (pass == 2) ? a1l[0][kt] : a1h[0][kt];
                    const unsigned* af1 = (pass == 2) ? a1l[1][kt] : a1h[1][kt];
                    mma16816(dAcc[0][nt], af0, b0, b1r);
                    mma16816(dAcc[1][nt], af1, b0, b1r);
                }
            }
        }

        // epilogue + gemm2, one kt2 (16 hidden cols) at a time
        #pragma unroll
        for (int kt2 = 0; kt2 < 4; kt2++) {
            unsigned a2h[2][4], a2l[2][4];
            #pragma unroll
            for (int part = 0; part < 2; part++) {
                int nt = 2 * kt2 + part;
                int c = nc * 64 + nt * 8 + tg * 2;
                float2 bv = *reinterpret_cast<const float2*>(b1 + c);
                #pragma unroll
                for (int mt = 0; mt < 2; mt++) {
                    float v0 = dAcc[mt][nt][0] + bv.x;
                    float v1 = dAcc[mt][nt][1] + bv.y;
                    float v2 = dAcc[mt][nt][2] + bv.x;
                    float v3 = dAcc[mt][nt][3] + bv.y;
                    float h0 = v0 * fminf(fmaxf(v0 + 3.f, 0.f), 6.f);
                    float h1 = v1 * fminf(fmaxf(v1 + 3.f, 0.f), 6.f);
                    float h2 = v2 * fminf(fmaxf(v2 + 3.f, 0.f), 6.f);
                    float h3 = v3 * fminf(fmaxf(v3 + 3.f, 0.f), 6.f);
                    __nv_bfloat162 p01 = __floats2bfloat162_rn(h0, h1);
                    __nv_bfloat162 p23 = __floats2bfloat162_rn(h2, h3);
                    float r0 = h0 - __bfloat162float(p01.x);
                    float r1 = h1 - __bfloat162float(p01.y);
                    float r2 = h2 - __bfloat162float(p23.x);
                    float r3 = h3 - __bfloat162float(p23.y);
                    __nv_bfloat162 q01 = __floats2bfloat162_rn(r0, r1);
                    __nv_bfloat162 q23 = __floats2bfloat162_rn(r2, r3);
                    a2h[mt][part * 2 + 0] = *reinterpret_cast<unsigned*>(&p01);
                    a2h[mt][part * 2 + 1] = *reinterpret_cast<unsigned*>(&p23);
                    a2l[mt][part * 2 + 0] = *reinterpret_cast<unsigned*>(&q01);
                    a2l[mt][part * 2 + 1] = *reinterpret_cast<unsigned*>(&q23);
                }
            }
            #pragma unroll
            for (int pass = 0; pass < 3; pass++) {
                const __nv_bfloat16* wp = (pass == 1) ? w2l : w2h;
                #pragma unroll
                for (int ntO = 0; ntO < 4; ntO++) {
                    int n = ntO * 8 + gid;
                    int k0 = nc * 64 + kt2 * 16 + tg * 2;
                    unsigned b0  = *reinterpret_cast<const unsigned*>(wp + n * 264 + k0);
                    unsigned b1r = *reinterpret_cast<const unsigned*>(wp + n * 264 + k0 + 8);
                    const unsigned* af0 = (pass == 2) ? a2l[0] : a2h[0];
                    const unsigned* af1 = (pass == 2) ? a2l[1] : a2h[1];
                    mma16816(outacc[0][ntO], af0, b0, b1r);
                    mma16816(outacc[1][ntO], af1, b0, b1r);
                }
            }
        }
    }

    // ---- residual add back into h ----
    if (TOKEN) {
        // h[n][m] += out[m][n]
        #pragma unroll
        for (int mt = 0; mt < 2; mt++)
        #pragma unroll
        for (int ntO = 0; ntO < 4; ntO++) {
            int mm = mt * 16 + gid;
            int nn = ntO * 8 + tg * 2;
            h[nn * 34 + mm]           += outacc[mt][ntO][0];
            h[(nn + 1) * 34 + mm]     += outacc[mt][ntO][1];
            h[nn * 34 + mm + 8]       += outacc[mt][ntO][2];
            h[(nn + 1) * 34 + mm + 8] += outacc[mt][ntO][3];
        }
    } else {
        #pragma unroll
        for (int mt = 0; mt < 2; mt++)
        #pragma unroll
        for (int ntO = 0; ntO < 4; ntO++) {
            int rr0 = mt * 16 + gid;
            int c = ntO * 8 + tg * 2;
            float2* p0 = reinterpret_cast<float2*>(h + rr0 * 34 + c);
            float2 v0 = *p0;
            v0.x += outacc[mt][ntO][0]; v0.y += outacc[mt][ntO][1];
            *p0 = v0;
            float2* p1 = reinterpret_cast<float2*>(h + (rr0 + 8) * 34 + c);
            float2 v1 = *p1;
            v1.x += outacc[mt][ntO][2]; v1.y += outacc[mt][ntO][3];
            *p1 = v1;
        }
    }
    __syncwarp();
}

extern __shared__ char smem_raw[];

__global__ __launch_bounds__(256, 1)
void mixer_kernel(
    const float* __restrict__ x,
    const float* __restrict__ conv_w, const float* __restrict__ conv_b,
    const float* __restrict__ fc0_w,  const float* __restrict__ fc0_b,
    const float* __restrict__ ln1_g,  const float* __restrict__ ln1_b,
    const float* __restrict__ w11,    const float* __restrict__ b11,
    const float* __restrict__ w12,    const float* __restrict__ b12,
    const float* __restrict__ ln2_g,  const float* __restrict__ ln2_b,
    const float* __restrict__ w21,    const float* __restrict__ b21,
    const float* __restrict__ w22,    const float* __restrict__ b22,
    const float* __restrict__ fc1_w,  const float* __restrict__ fc1_b,
    const float* __restrict__ fcout_w,const float* __restrict__ fcout_b,
    float* __restrict__ out, int B)
{
    const int tid = threadIdx.x;
    const int lane = tid & 31;
    const int wid = tid >> 5;      // 0..7, one element per warp

    float* sH   = reinterpret_cast<float*>(smem_raw + OFF_H);
    float* sSt  = reinterpret_cast<float*>(smem_raw + OFF_ST);
    float* sB1t = reinterpret_cast<float*>(smem_raw + OFF_B1T);
    float* sB1c = reinterpret_cast<float*>(smem_raw + OFF_B1C);
    float* sB2t = reinterpret_cast<float*>(smem_raw + OFF_B2T);
    float* sB2c = reinterpret_cast<float*>(smem_raw + OFF_B2C);
    float* sL1g = reinterpret_cast<float*>(smem_raw + OFF_LN1G);
    float* sL1b = reinterpret_cast<float*>(smem_raw + OFF_LN1B);
    float* sL2g = reinterpret_cast<float*>(smem_raw + OFF_LN2G);
    float* sL2b = reinterpret_cast<float*>(smem_raw + OFF_LN2B);
    __nv_bfloat16* w1th = reinterpret_cast<__nv_bfloat16*>(smem_raw + OFF_W1TH);
    __nv_bfloat16* w1tl = reinterpret_cast<__nv_bfloat16*>(smem_raw + OFF_W1TL);
    __nv_bfloat16* w1ch = reinterpret_cast<__nv_bfloat16*>(smem_raw + OFF_W1CH);
    __nv_bfloat16* w1cl = reinterpret_cast<__nv_bfloat16*>(smem_raw + OFF_W1CL);
    __nv_bfloat16* w2th = reinterpret_cast<__nv_bfloat16*>(smem_raw + OFF_W2TH);
    __nv_bfloat16* w2tl = reinterpret_cast<__nv_bfloat16*>(smem_raw + OFF_W2TL);
    __nv_bfloat16* w2ch = reinterpret_cast<__nv_bfloat16*>(smem_raw + OFF_W2CH);
    __nv_bfloat16* w2cl = reinterpret_cast<__nv_bfloat16*>(smem_raw + OFF_W2CL);
    float* sFw = reinterpret_cast<float*>(smem_raw + OFF_WT);          // fp32 staging reuse
    float* sFo = reinterpret_cast<float*>(smem_raw + OFF_WT + 16384);  // fcout staging

    const int eb = blockIdx.x * 8 + wid;
    const bool act = (eb < B);
    float* h  = sH + wid * (32 * 34);
    float* st = sSt + wid * 64;

    // ---- stage fc0 weights, preprocess (conv1x1 + fc0) ----
    for (int i = tid; i < 1024; i += 256) sFw[i] = fc0_w[i];
    if (tid < 32) sB1t[tid] = fc0_b[tid];
    __syncthreads();

    if (act) {
        const float cw0 = conv_w[0], cw1 = conv_w[1], cw2 = conv_w[2];
        const float cb  = conv_b[0];
        const float* xb = x + (size_t)eb * 3072 + lane * 32;
        float2 gp[16];
        #pragma unroll
        for (int qq = 0; qq < 8; qq++) {
            float4 v0 = *reinterpret_cast<const float4*>(xb + qq * 4);
            float4 v1 = *reinterpret_cast<const float4*>(xb + 1024 + qq * 4);
            float4 v2 = *reinterpret_cast<const float4*>(xb + 2048 + qq * 4);
            gp[2 * qq]     = make_float2(cw0 * v0.x + cw1 * v1.x + cw2 * v2.x + cb,
                                         cw0 * v0.y + cw1 * v1.y + cw2 * v2.y + cb);
            gp[2 * qq + 1] = make_float2(cw0 * v0.z + cw1 * v1.z + cw2 * v2.z + cb,
                                         cw0 * v0.w + cw1 * v1.w + cw2 * v2.w + cb);
        }
        for (int j = 0; j < 32; j++) {
            const float4* wq = reinterpret_cast<const float4*>(sFw + j * 32);
            float2 acc = make_float2(0.f, 0.f), accb = make_float2(0.f, 0.f);
            #pragma unroll
            for (int qq = 0; qq < 8; qq++) {
                float4 w = wq[qq];
                acc  = ffma2(gp[2 * qq],     make_float2(w.x, w.y), acc);
                accb = ffma2(gp[2 * qq + 1], make_float2(w.z, w.w), accb);
            }
            float2 sv = fadd2(acc, accb);
            h[lane * 34 + j] = sv.x + sv.y + sB1t[j];
        }
    }
    __syncthreads();

    // ---- 8 layers x 2 repeats ----
    for (int l = 0; l < 8; l++) {
        // stage bf16 hi/lo weight planes for this layer
        {
            const float* g11 = w11 + l * 8192;
            const float* g21 = w21 + l * 8192;
            for (int i = tid; i < 8192; i += 256) {
                int d = i >> 5, k = i & 31;
                float v = g11[i];
                __nv_bfloat16 hi = __float2bfloat16(v);
                w1th[d * 40 + k] = hi;
                w1tl[d * 40 + k] = __float2bfloat16(v - __bfloat162float(hi));
                float u = g21[i];
                __nv_bfloat16 hu = __float2bfloat16(u);
                w1ch[d * 40 + k] = hu;
                w1cl[d * 40 + k] = __float2bfloat16(u - __bfloat162float(hu));
            }
            const float* g12 = w12 + l * 8192;
            const float* g22 = w22 + l * 8192;
            for (int i = tid; i < 8192; i += 256) {
                int n = i >> 8, k = i & 255;
                float v = g12[i] * (1.0f / 6.0f);
                __nv_bfloat16 hi = __float2bfloat16(v);
                w2th[n * 264 + k] = hi;
                w2tl[n * 264 + k] = __float2bfloat16(v - __bfloat162float(hi));
                float u = g22[i] * (1.0f / 6.0f);
                __nv_bfloat16 hu = __float2bfloat16(u);
                w2ch[n * 264 + k] = hu;
                w2cl[n * 264 + k] = __float2bfloat16(u - __bfloat162float(hu));
            }
            if (tid < 256) { sB1t[tid] = b11[l * 256 + tid]; sB1c[tid] = b21[l * 256 + tid]; }
            if (tid < 32) {
                sB2t[tid] = b12[l * 32 + tid];
                sB2c[tid] = b22[l * 32 + tid];
                sL1g[tid] = ln1_g[l * 32 + tid];
                sL1b[tid] = ln1_b[l * 32 + tid];
                sL2g[tid] = ln2_g[l * 32 + tid];
                sL2b[tid] = ln2_b[l * 32 + tid];
            }
        }
        __syncthreads();

        if (act) {
            for (int rep = 0; rep < 2; rep++) {
                mix_branch_mma<true >(h, st, w1th, w1tl, w2th, w2tl,
                                      sB1t, sB2t, sL1g, sL1b, lane);
                mix_branch_mma<false>(h, st, w1ch, w1cl, w2ch, w2cl,
                                      sB1c, sB2c, sL2g, sL2b, lane);
            }
        }
        __syncthreads();
    }

    // ---- head: fc1 + hardswish + avgpool(32) + fcout ----
    {
        const float4* s1 = reinterpret_cast<const float4*>(fc1_w);
        float4* d1 = reinterpret_cast<float4*>(sFw);
        for (int i = tid; i < 1024; i += 256) d1[i] = s1[i];
        for (int i = tid; i < 1280; i += 256) sFo[i] = fcout_w[i];
        if (tid < 128) sB1t[tid] = fc1_b[tid];
        if (tid < 10)  sB2t[tid] = fcout_b[tid];
    }
    __syncthreads();

    if (act) {
        float2 ap[16];
        #pragma unroll
        for (int t = 0; t < 16; t++)
            ap[t] = *reinterpret_cast<const float2*>(h + lane * 34 + 2 * t);
        float pool[4] = {0.f, 0.f, 0.f, 0.f};
        for (int d = 0; d < 128; d++) {
            const float4* wq = reinterpret_cast<const float4*>(sFw + d * 32);
            float2 acc = make_float2(0.f, 0.f), accb = make_float2(0.f, 0.f);
            #pragma unroll
            for (int qq = 0; qq < 8; qq++) {
                float4 w = wq[qq];
                acc  = ffma2(ap[2 * qq],     make_float2(w.x, w.y), acc);
                accb = ffma2(ap[2 * qq + 1], make_float2(w.z, w.w), accb);
            }
            float2 sv = fadd2(acc, accb);
            float v = sv.x + sv.y + sB1t[d];
            float y = v * fminf(fmaxf(v + 3.0f, 0.0f), 6.0f) * (1.0f / 6.0f);
            pool[d >> 5] += y;
        }
        #pragma unroll
        for (int p = 0; p < 4; p++) pool[p] *= (1.0f / 32.0f);
        #pragma unroll
        for (int o = 0; o < 10; o++) {
            float4 wv = *reinterpret_cast<const float4*>(sFo + o * 128 + lane * 4);
            float v = pool[0] * wv.x + pool[1] * wv.y + pool[2] * wv.z + pool[3] * wv.w;
            #pragma unroll
            for (int sft = 16; sft > 0; sft >>= 1)
                v += __shfl_xor_sync(0xffffffffu, v, sft);
            if (lane == 0) out[(size_t)eb * 10 + o] = v + sB2t[o];
        }
    }
}

extern "C" void kernel_launch(void* const* d_in, const int* in_sizes, int n_in,
                              void* d_out, int out_size) {
    const float* x       = (const float*)d_in[0];
    const float* conv_w  = (const float*)d_in[1];
    const float* conv_b  = (const float*)d_in[2];
    const float* fc0_w   = (const float*)d_in[3];
    const float* fc0_b   = (const float*)d_in[4];
    const float* ln1_g   = (const float*)d_in[5];
    const float* ln1_b   = (const float*)d_in[6];
    const float* w11     = (const float*)d_in[7];
    const float* b11     = (const float*)d_in[8];
    const float* w12     = (const float*)d_in[9];
    const float* b12     = (const float*)d_in[10];
    const float* ln2_g   = (const float*)d_in[11];
    const float* ln2_b   = (const float*)d_in[12];
    const float* w21     = (const float*)d_in[13];
    const float* b21     = (const float*)d_in[14];
    const float* w22     = (const float*)d_in[15];
    const float* b22     = (const float*)d_in[16];
    const float* fc1_w   = (const float*)d_in[17];
    const float* fc1_b   = (const float*)d_in[18];
    const float* fcout_w = (const float*)d_in[19];
    const float* fcout_b = (const float*)d_in[20];
    float* out = (float*)d_out;

    const int B = in_sizes[0] / 3072;
    const int blocks = (B + 7) / 8;

    cudaFuncSetAttribute(mixer_kernel,
                         cudaFuncAttributeMaxDynamicSharedMemorySize,
                         SMEM_BYTES);
    mixer_kernel<<<blocks, 256, SMEM_BYTES>>>(
        x, conv_w, conv_b, fc0_w, fc0_b, ln1_g, ln1_b,
        w11, b11, w12, b12, ln2_g, ln2_b, w21, b21, w22, b22,
        fc1_w, fc1_b, fcout_w, fcout_b, out, B);
}